// round 1
// baseline (speedup 1.0000x reference)
#include <cuda_runtime.h>

// SparseConv1D: out[b,o,l] = sum_i sum_k w[o,i,k] * x_pad[b,i,l+d_k]
// x: [16,64,4096] f32, w: [64,64,32] f32, out: [16,64,4096] f32.
// Out-of-range taps (l+d < 0 or >= 4096) read zero (matches reference's
// circular-index-into-zero-pad construction).

#define K_TAPS   32
#define CIN      64
#define COUT     64
#define LEN      4096
#define BATCH    16
#define LOWPAD   512
#define HIGHPAD  256
#define THREADS  128
#define P        8                      // positions per thread
#define OT       4                      // outputs per block
#define OPAIRS   (OT/2)
#define LTILE    (THREADS * P)          // 1024
#define WIN      (LTILE + LOWPAD + HIGHPAD)  // 1792

// Packed fp32x2 FMA (Blackwell FFMA2). Only reachable via PTX.
__device__ __forceinline__ float2 ffma2(float2 a, float2 b, float2 c) {
    float2 d;
    asm("fma.rn.f32x2 %0, %1, %2, %3;"
        : "=l"(*reinterpret_cast<unsigned long long*>(&d))
        : "l"(*reinterpret_cast<unsigned long long*>(&a)),
          "l"(*reinterpret_cast<unsigned long long*>(&b)),
          "l"(*reinterpret_cast<unsigned long long*>(&c)));
    return d;
}

__global__ __launch_bounds__(THREADS)
void sk_conv_kernel(const float* __restrict__ x,
                    const float* __restrict__ w,
                    float* __restrict__ out) {
    // Tap offsets (compile-time; fully unrolled below so they fold to immediates)
    constexpr int SK[K_TAPS] = {
        -512,-256,-128,-96,-64,-48,-32,-24,-16,-12,-8,-6,-4,-3,-2,-1,
         0,1,2,3,4,6,8,12,16,24,32,48,64,96,128,256
    };

    // w pairs over adjacent outputs: w_sh[i][k][q] = (w[o0+2q][i][k], w[o0+2q+1][i][k])
    __shared__ float2 w_sh[CIN][K_TAPS][OPAIRS];   // 32 KB
    // x window duplicated (v,v) so any tap offset is an aligned LDS.64
    __shared__ float2 x_dup[WIN];                  // 14 KB

    const int tid = threadIdx.x;
    const int l0  = blockIdx.x * LTILE;
    const int o0  = blockIdx.y * OT;
    const int b   = blockIdx.z;

    // ---- load weight slice for this block's OT outputs ----
    for (int idx = tid; idx < CIN * K_TAPS * OPAIRS; idx += THREADS) {
        int q = idx & (OPAIRS - 1);
        int k = (idx / OPAIRS) & (K_TAPS - 1);
        int i = idx / (K_TAPS * OPAIRS);
        const float* wp = w + ((size_t)(o0 + 2 * q) * CIN + i) * K_TAPS + k;
        w_sh[i][k][q] = make_float2(wp[0], wp[CIN * K_TAPS]);
    }

    float2 acc[P][OPAIRS];
#pragma unroll
    for (int p = 0; p < P; ++p)
#pragma unroll
        for (int q = 0; q < OPAIRS; ++q) acc[p][q] = make_float2(0.f, 0.f);

    const float* xb = x + (size_t)b * CIN * LEN;

    for (int i = 0; i < CIN; ++i) {
        __syncthreads();   // previous window fully consumed (also covers w_sh on i==0)
        const float* xi = xb + i * LEN;
        for (int j = tid; j < WIN; j += THREADS) {
            int g = l0 - LOWPAD + j;
            float v = (g >= 0 && g < LEN) ? __ldg(xi + g) : 0.f;
            x_dup[j] = make_float2(v, v);
        }
        __syncthreads();

#pragma unroll
        for (int k = 0; k < K_TAPS; ++k) {
            const int d = SK[k];
            float2 w0 = w_sh[i][k][0];
            float2 w1 = w_sh[i][k][1];
#pragma unroll
            for (int p = 0; p < P; ++p) {
                float2 xv = x_dup[tid + p * THREADS + LOWPAD + d];
                acc[p][0] = ffma2(w0, xv, acc[p][0]);
                acc[p][1] = ffma2(w1, xv, acc[p][1]);
            }
        }
    }

    // ---- store ----
#pragma unroll
    for (int p = 0; p < P; ++p) {
        int l = l0 + tid + p * THREADS;
#pragma unroll
        for (int q = 0; q < OPAIRS; ++q) {
            int o = o0 + 2 * q;
            out[((size_t)b * COUT + o)     * LEN + l] = acc[p][q].x;
            out[((size_t)b * COUT + o + 1) * LEN + l] = acc[p][q].y;
        }
    }
}

extern "C" void kernel_launch(void* const* d_in, const int* in_sizes, int n_in,
                              void* d_out, int out_size) {
    const float* x = (const float*)d_in[0];   // [16,64,4096]
    const float* w = (const float*)d_in[1];   // [64,64,32]
    float* out = (float*)d_out;               // [16,64,4096]
    dim3 grid(LEN / LTILE, COUT / OT, BATCH); // (4, 16, 16) = 1024 blocks
    sk_conv_kernel<<<grid, THREADS>>>(x, w, out);
}

// round 2
// speedup vs baseline: 1.0186x; 1.0186x over previous
#include <cuda_runtime.h>

// SparseConv1D: out[b,o,l] = sum_i sum_k w[o,i,k] * x[b,i,l+d_k] (zero pad OOR)
// x: [16,64,4096] f32, w: [64,64,32] f32, out: [16,64,4096] f32.
//
// Register tile per thread: 8 outputs x 8 positions (4 position-pairs as float2).
// x pairs come from two shifted smem copies (xa = window, xb = window<<1 float)
// so every tap offset is an aligned, coalesced LDS.64.

#define K_TAPS   32
#define CIN      64
#define COUT     64
#define LEN      4096
#define BATCH    16
#define LOWPAD   512
#define THREADS  128
#define NOUT     8                        // outputs per block/thread
#define NPAIR    4                        // position-pairs per thread
#define LTILE    (THREADS * NPAIR * 2)    // 1024 positions per block
#define WIN      (LTILE + 768)            // 1792 window floats
#define W2_ELEMS (CIN * NOUT * (K_TAPS/2))  // float2 count = 8192 (64KB)
#define SMEM_BYTES (W2_ELEMS * 8 + 2 * WIN * 4)  // 65536 + 14336 = 79872

// Packed fp32x2 FMA (Blackwell FFMA2), PTX-only.
__device__ __forceinline__ float2 ffma2(float2 a, float2 b, float2 c) {
    float2 d;
    asm("fma.rn.f32x2 %0, %1, %2, %3;"
        : "=l"(*reinterpret_cast<unsigned long long*>(&d))
        : "l"(*reinterpret_cast<unsigned long long*>(&a)),
          "l"(*reinterpret_cast<unsigned long long*>(&b)),
          "l"(*reinterpret_cast<unsigned long long*>(&c)));
    return d;
}

__global__ __launch_bounds__(THREADS)
void sk_conv_kernel(const float* __restrict__ x,
                    const float* __restrict__ w,
                    float* __restrict__ out) {
    constexpr int SK[K_TAPS] = {
        -512,-256,-128,-96,-64,-48,-32,-24,-16,-12,-8,-6,-4,-3,-2,-1,
         0,1,2,3,4,6,8,12,16,24,32,48,64,96,128,256
    };

    extern __shared__ float smem[];
    float2* w2 = reinterpret_cast<float2*>(smem);        // [i][o][kk] kk=k/2
    float*  xa = smem + W2_ELEMS * 2;                    // win[j]
    float*  xb = xa + WIN;                               // win[j+1]

    const int tid = threadIdx.x;
    const int l0  = blockIdx.x * LTILE;
    const int o0  = blockIdx.y * NOUT;
    const int b   = blockIdx.z;

    // ---- stage weights: w2[(i*NOUT+o)*16+kk] = (w[o0+o,i,2kk], w[o0+o,i,2kk+1])
    for (int idx = tid; idx < W2_ELEMS; idx += THREADS) {
        int kk = idx & 15;
        int o  = (idx >> 4) & (NOUT - 1);
        int i  = idx >> 7;
        w2[idx] = *reinterpret_cast<const float2*>(
            w + ((size_t)(o0 + o) * CIN + i) * K_TAPS + 2 * kk);
    }

    float2 acc[NOUT][NPAIR];
#pragma unroll
    for (int o = 0; o < NOUT; ++o)
#pragma unroll
        for (int p = 0; p < NPAIR; ++p) acc[o][p] = make_float2(0.f, 0.f);

    const float* xbase = x + (size_t)b * CIN * LEN;
    const float2* xa2 = reinterpret_cast<const float2*>(xa);
    const float2* xb2 = reinterpret_cast<const float2*>(xb);

    for (int i = 0; i < CIN; ++i) {
        __syncthreads();   // previous window consumed (covers w2 on i==0)
        const float* xi = xbase + i * LEN;
        // fill xa (window) and xb (window shifted by 1 float)
        for (int j2 = tid; j2 < WIN / 2; j2 += THREADS) {
            int j = 2 * j2;
            int g = l0 - LOWPAD + j;
            float2 v;
            if (g >= 0 && g + 1 < LEN) {
                v = *reinterpret_cast<const float2*>(xi + g);
            } else {
                v.x = (g >= 0     && g     < LEN) ? xi[g]     : 0.f;
                v.y = (g + 1 >= 0 && g + 1 < LEN) ? xi[g + 1] : 0.f;
            }
            reinterpret_cast<float2*>(xa)[j2] = v;
            if (j > 0) xb[j - 1] = v.x;
            xb[j] = v.y;
        }
        __syncthreads();

#pragma unroll
        for (int kk = 0; kk < K_TAPS / 2; ++kk) {
            float2 wv[NOUT];
#pragma unroll
            for (int o = 0; o < NOUT; ++o)
                wv[o] = w2[(i * NOUT + o) * (K_TAPS / 2) + kk];

            // ---- tap 2kk ----
            {
                constexpr_taps:;
                const int d = SK[2 * kk];
                const float2* xs = (d & 1) ? xb2 : xa2;
                const int off = (d & 1) ? (d + LOWPAD - 1) / 2
                                        : (d + LOWPAD) / 2;
                float2 wd[NOUT];
#pragma unroll
                for (int o = 0; o < NOUT; ++o)
                    wd[o] = make_float2(wv[o].x, wv[o].x);
#pragma unroll
                for (int p = 0; p < NPAIR; ++p) {
                    float2 xv = xs[tid + THREADS * p + off];
#pragma unroll
                    for (int o = 0; o < NOUT; ++o)
                        acc[o][p] = ffma2(wd[o], xv, acc[o][p]);
                }
            }
            // ---- tap 2kk+1 ----
            {
                const int d = SK[2 * kk + 1];
                const float2* xs = (d & 1) ? xb2 : xa2;
                const int off = (d & 1) ? (d + LOWPAD - 1) / 2
                                        : (d + LOWPAD) / 2;
                float2 wd[NOUT];
#pragma unroll
                for (int o = 0; o < NOUT; ++o)
                    wd[o] = make_float2(wv[o].y, wv[o].y);
#pragma unroll
                for (int p = 0; p < NPAIR; ++p) {
                    float2 xv = xs[tid + THREADS * p + off];
#pragma unroll
                    for (int o = 0; o < NOUT; ++o)
                        acc[o][p] = ffma2(wd[o], xv, acc[o][p]);
                }
            }
        }
    }

    // ---- store: position pair (l, l+1) is a contiguous float2 ----
#pragma unroll
    for (int o = 0; o < NOUT; ++o) {
        float2* op = reinterpret_cast<float2*>(
            out + ((size_t)b * COUT + o0 + o) * LEN + l0);
#pragma unroll
        for (int p = 0; p < NPAIR; ++p)
            op[tid + THREADS * p] = acc[o][p];
    }
}

extern "C" void kernel_launch(void* const* d_in, const int* in_sizes, int n_in,
                              void* d_out, int out_size) {
    const float* x = (const float*)d_in[0];   // [16,64,4096]
    const float* w = (const float*)d_in[1];   // [64,64,32]
    float* out = (float*)d_out;               // [16,64,4096]
    cudaFuncSetAttribute(sk_conv_kernel,
                         cudaFuncAttributeMaxDynamicSharedMemorySize,
                         SMEM_BYTES);
    dim3 grid(LEN / LTILE, COUT / NOUT, BATCH);  // (4, 8, 16) = 512 blocks
    sk_conv_kernel<<<grid, THREADS, SMEM_BYTES>>>(x, w, out);
}

// round 3
// speedup vs baseline: 1.1619x; 1.1407x over previous
#include <cuda_runtime.h>

// SparseConv1D: out[b,o,l] = sum_i sum_k w[o,i,k] * x[b,i,l+d_k] (zero pad OOR)
// x: [16,64,4096] f32, w: [64,64,32] f32, out: [16,64,4096] f32.
//
// Per-thread register tile: 8 outputs x 8 positions (4 float2 position-pairs).
// x pairs served by two shifted smem windows (xa = win[j], xb = win[j+1]) so
// every tap parity is an aligned coalesced LDS.64. Weights staged per-i,
// pre-duplicated (w,w), prefetched one i ahead.

#define K_TAPS   32
#define CIN      64
#define COUT     64
#define LEN      4096
#define BATCH    16
#define LOWPAD   512
#define THREADS  128
#define NOUT     8
#define NPAIR    4
#define LTILE    (THREADS * NPAIR * 2)    // 1024
#define WIN      (LTILE + 768)            // 1792

// Packed fp32x2 FMA (Blackwell FFMA2), PTX-only.
__device__ __forceinline__ float2 ffma2(float2 a, float2 b, float2 c) {
    float2 d;
    asm("fma.rn.f32x2 %0, %1, %2, %3;"
        : "=l"(*reinterpret_cast<unsigned long long*>(&d))
        : "l"(*reinterpret_cast<unsigned long long*>(&a)),
          "l"(*reinterpret_cast<unsigned long long*>(&b)),
          "l"(*reinterpret_cast<unsigned long long*>(&c)));
    return d;
}

__global__ __launch_bounds__(THREADS, 4)
void sk_conv_kernel(const float* __restrict__ x,
                    const float* __restrict__ w,
                    float* __restrict__ out) {
    constexpr int SK[K_TAPS] = {
        -512,-256,-128,-96,-64,-48,-32,-24,-16,-12,-8,-6,-4,-3,-2,-1,
         0,1,2,3,4,6,8,12,16,24,32,48,64,96,128,256
    };

    __shared__ float2 wdup[K_TAPS * NOUT];   // [k][o] = (w,w)  : 2 KB
    __shared__ float  xa[WIN];               // win[j]           : 7 KB
    __shared__ float  xb[WIN];               // win[j+1]         : 7 KB

    const int tid = threadIdx.x;
    const int l0  = blockIdx.x * LTILE;
    const int o0  = blockIdx.y * NOUT;
    const int b   = blockIdx.z;

    // per-i weight slice: 256 elems, 2 per thread. idx -> o = idx&7, k = idx>>3
    const int oA = o0 + (tid & 7),        kA = tid >> 3;
    const int oB = o0 + ((tid + THREADS) & 7), kB = (tid + THREADS) >> 3;
    const float* wA = w + ((size_t)oA * CIN) * K_TAPS + kA;
    const float* wB = w + ((size_t)oB * CIN) * K_TAPS + kB;

    float wra = __ldg(wA);          // prefetch i = 0
    float wrb = __ldg(wB);

    float2 acc[NOUT][NPAIR];
#pragma unroll
    for (int o = 0; o < NOUT; ++o)
#pragma unroll
        for (int p = 0; p < NPAIR; ++p) acc[o][p] = make_float2(0.f, 0.f);

    const float* xbase = x + (size_t)b * CIN * LEN;
    const float2* xa2 = reinterpret_cast<const float2*>(xa);
    const float2* xb2 = reinterpret_cast<const float2*>(xb);

    for (int i = 0; i < CIN; ++i) {
        __syncthreads();   // previous window + weights fully consumed

        // stage duplicated weights for this i
        wdup[tid]           = make_float2(wra, wra);
        wdup[tid + THREADS] = make_float2(wrb, wrb);

        // fill x windows (xa aligned, xb shifted by one float)
        const float* xi = xbase + i * LEN;
#pragma unroll
        for (int it = 0; it < WIN / 2 / THREADS; ++it) {
            int j2 = tid + it * THREADS;
            int j  = 2 * j2;
            int g  = l0 - LOWPAD + j;
            float2 v;
            if (g >= 0 && g + 1 < LEN) {
                v = *reinterpret_cast<const float2*>(xi + g);
            } else {
                v.x = (g >= 0     && g     < LEN) ? xi[g]     : 0.f;
                v.y = (g + 1 >= 0 && g + 1 < LEN) ? xi[g + 1] : 0.f;
            }
            reinterpret_cast<float2*>(xa)[j2] = v;
            if (j > 0) xb[j - 1] = v.x;
            xb[j] = v.y;
        }

        // prefetch next i's weights (hidden under compute)
        if (i + 1 < CIN) {
            wra = __ldg(wA + (i + 1) * K_TAPS);
            wrb = __ldg(wB + (i + 1) * K_TAPS);
        }

        __syncthreads();

#pragma unroll
        for (int k = 0; k < K_TAPS; ++k) {
            const int d   = SK[k];
            const float2* xs = (d & 1) ? xb2 : xa2;
            const int off = (d & 1) ? (d + LOWPAD - 1) / 2 : (d + LOWPAD) / 2;

            float2 xv[NPAIR];
#pragma unroll
            for (int p = 0; p < NPAIR; ++p)
                xv[p] = xs[tid + THREADS * p + off];

#pragma unroll
            for (int o = 0; o < NOUT; ++o) {
                float2 wv = wdup[k * NOUT + o];   // broadcast, pre-duplicated
#pragma unroll
                for (int p = 0; p < NPAIR; ++p)
                    acc[o][p] = ffma2(wv, xv[p], acc[o][p]);
            }
        }
    }

    // store: position pair (l, l+1) is a contiguous float2
#pragma unroll
    for (int o = 0; o < NOUT; ++o) {
        float2* op = reinterpret_cast<float2*>(
            out + ((size_t)b * COUT + o0 + o) * LEN + l0);
#pragma unroll
        for (int p = 0; p < NPAIR; ++p)
            op[tid + THREADS * p] = acc[o][p];
    }
}

extern "C" void kernel_launch(void* const* d_in, const int* in_sizes, int n_in,
                              void* d_out, int out_size) {
    const float* x = (const float*)d_in[0];   // [16,64,4096]
    const float* w = (const float*)d_in[1];   // [64,64,32]
    float* out = (float*)d_out;               // [16,64,4096]
    dim3 grid(LEN / LTILE, COUT / NOUT, BATCH);  // (4, 8, 16) = 512 blocks
    sk_conv_kernel<<<grid, THREADS>>>(x, w, out);
}